// round 3
// baseline (speedup 1.0000x reference)
#include <cuda_runtime.h>

#define NN 100000
#define NE 1000000
#define FIN 128
#define HH 8
#define HF 256
#define CC 16
#define NB_SCAN ((NN + 1023) / 1024)

// ---------------- scratch (static device globals; no allocation) ----------------
__device__ __align__(16) float g_h1[NN * HF];     // layer-1 pre-aggregation features
__device__ __align__(16) float g_out1[NN * HF];   // elu(layer-1 output)
__device__ __align__(16) float g_s1s[NN * HH];
__device__ __align__(16) float g_s1d[NN * HH];
__device__ __align__(16) float g_h2[NN * CC];
__device__ float g_s2s[NN];
__device__ float g_s2d[NN];
__device__ int g_deg[NN];
__device__ int g_cur[NN];
__device__ int g_rs[NN + 1];
__device__ int g_csrc[NE];
__device__ int g_bsum[128];

// ---------------- CSR construction ----------------
__global__ void k_zero() {
    int i = blockIdx.x * blockDim.x + threadIdx.x;
    if (i < NN) { g_deg[i] = 0; g_cur[i] = 0; }
}

__global__ void k_hist(const int* __restrict__ ei) {
    int e = blockIdx.x * blockDim.x + threadIdx.x;
    if (e < NE) atomicAdd(&g_deg[ei[NE + e]], 1);
}

__global__ void k_scanA() {
    __shared__ int s[1024];
    int t = threadIdx.x;
    int i = blockIdx.x * 1024 + t;
    int v = (i < NN) ? g_deg[i] : 0;
    s[t] = v;
    __syncthreads();
    for (int off = 1; off < 1024; off <<= 1) {
        int u = (t >= off) ? s[t - off] : 0;
        __syncthreads();
        s[t] += u;
        __syncthreads();
    }
    if (i < NN) g_rs[i] = s[t] - v;           // block-local exclusive
    if (t == 1023) g_bsum[blockIdx.x] = s[1023];
}

__global__ void k_scanB() {
    __shared__ int s[128];
    int t = threadIdx.x;
    int v = (t < NB_SCAN) ? g_bsum[t] : 0;
    s[t] = v;
    __syncthreads();
    for (int off = 1; off < 128; off <<= 1) {
        int u = (t >= off) ? s[t - off] : 0;
        __syncthreads();
        s[t] += u;
        __syncthreads();
    }
    if (t < NB_SCAN) g_bsum[t] = s[t] - v;    // exclusive block offsets
}

__global__ void k_scanC() {
    int i = blockIdx.x * blockDim.x + threadIdx.x;
    if (i < NN) g_rs[i] += g_bsum[i >> 10];
    if (i == 0) g_rs[NN] = NE;
}

__global__ void k_scatter(const int* __restrict__ ei) {
    int e = blockIdx.x * blockDim.x + threadIdx.x;
    if (e < NE) {
        int d = ei[NE + e];
        int p = atomicAdd(&g_cur[d], 1);
        g_csrc[g_rs[d] + p] = ei[e];
    }
}

// ---------------- GEMM1: h1 = x @ W1  (100000x128 @ 128x256) ----------------
// 64x64 output tile, K split into 2 chunks of 64 -> 32KB static smem.
__global__ void __launch_bounds__(256) k_gemm1(const float* __restrict__ x,
                                               const float* __restrict__ W1) {
    __shared__ __align__(16) float Xs[64][64];  // [k][m]
    __shared__ __align__(16) float Ws[64][64];  // [k][n]
    int bm = blockIdx.x * 64;
    int bn = blockIdx.y * 64;
    int t = threadIdx.x;
    int tx = t & 15, ty = t >> 4;
    float acc[4][4] = {};

#pragma unroll
    for (int kt = 0; kt < 2; kt++) {
        // load X tile: 64 rows x 64 k values (as [k][m])
#pragma unroll
        for (int it = 0; it < 4; it++) {
            int i = t + 256 * it;               // 0..1023
            int r = i >> 4, k4 = i & 15;        // row 0..63, k4 0..15
            int row = bm + r;
            float4 v = (row < NN)
                ? *(const float4*)(x + row * FIN + kt * 64 + k4 * 4)
                : make_float4(0.f, 0.f, 0.f, 0.f);
            Xs[k4 * 4 + 0][r] = v.x;
            Xs[k4 * 4 + 1][r] = v.y;
            Xs[k4 * 4 + 2][r] = v.z;
            Xs[k4 * 4 + 3][r] = v.w;
        }
        // load W tile: 64 k x 64 n (as [k][n])
#pragma unroll
        for (int it = 0; it < 4; it++) {
            int i = t + 256 * it;               // 0..1023
            int k = i >> 4, c4 = i & 15;
            *(float4*)&Ws[k][c4 * 4] =
                *(const float4*)(W1 + (kt * 64 + k) * HF + bn + c4 * 4);
        }
        __syncthreads();

#pragma unroll 16
        for (int k = 0; k < 64; k++) {
            float4 a = *(const float4*)&Xs[k][ty * 4];
            float4 b = *(const float4*)&Ws[k][tx * 4];
            acc[0][0] += a.x * b.x; acc[0][1] += a.x * b.y; acc[0][2] += a.x * b.z; acc[0][3] += a.x * b.w;
            acc[1][0] += a.y * b.x; acc[1][1] += a.y * b.y; acc[1][2] += a.y * b.z; acc[1][3] += a.y * b.w;
            acc[2][0] += a.z * b.x; acc[2][1] += a.z * b.y; acc[2][2] += a.z * b.z; acc[2][3] += a.z * b.w;
            acc[3][0] += a.w * b.x; acc[3][1] += a.w * b.y; acc[3][2] += a.w * b.z; acc[3][3] += a.w * b.w;
        }
        __syncthreads();
    }
#pragma unroll
    for (int i = 0; i < 4; i++) {
        int row = bm + ty * 4 + i;
        if (row < NN)
            *(float4*)&g_h1[row * HF + bn + tx * 4] =
                make_float4(acc[i][0], acc[i][1], acc[i][2], acc[i][3]);
    }
}

// ---------------- per-node attention dot products, layer 1 ----------------
__global__ void k_sdot1(const float* __restrict__ as, const float* __restrict__ ad) {
    int gt = blockIdx.x * blockDim.x + threadIdx.x;
    int w = gt >> 5;
    int lane = threadIdx.x & 31;
    if (w >= NN) return;
    const float* hp = g_h1 + w * HF;
    float hv[8];
#pragma unroll
    for (int k = 0; k < 8; k++) hv[k] = hp[k * 32 + lane];
#pragma unroll
    for (int h = 0; h < 8; h++) {
        float ps = hv[h] * as[h * 32 + lane];
        float pd = hv[h] * ad[h * 32 + lane];
#pragma unroll
        for (int off = 16; off; off >>= 1) {
            ps += __shfl_xor_sync(0xFFFFFFFFu, ps, off);
            pd += __shfl_xor_sync(0xFFFFFFFFu, pd, off);
        }
        if (lane == 0) { g_s1s[w * 8 + h] = ps; g_s1d[w * 8 + h] = pd; }
    }
}

// ---------------- layer-1 aggregation: warp per destination node ----------------
__global__ void k_agg1(const float* __restrict__ b1) {
    int gt = blockIdx.x * blockDim.x + threadIdx.x;
    int w = gt >> 5;
    int lane = threadIdx.x & 31;
    if (w >= NN) return;
    int rs = g_rs[w], re = g_rs[w + 1];
    int deg = re - rs;
    float acc[8] = {0.f, 0.f, 0.f, 0.f, 0.f, 0.f, 0.f, 0.f};
    if (deg > 0) {
        float sd[8];
#pragma unroll
        for (int h = 0; h < 8; h++) sd[h] = g_s1d[w * 8 + h];
        float mx[8];
#pragma unroll
        for (int h = 0; h < 8; h++) mx[h] = -1e30f;
        // pass 1: per-head segment max
        for (int j = lane; j < deg; j += 32) {
            int s = g_csrc[rs + j];
#pragma unroll
            for (int h = 0; h < 8; h++) {
                float sc = g_s1s[s * 8 + h] + sd[h];
                sc = sc > 0.f ? sc : 0.2f * sc;
                mx[h] = fmaxf(mx[h], sc);
            }
        }
#pragma unroll
        for (int h = 0; h < 8; h++)
#pragma unroll
            for (int off = 16; off; off >>= 1)
                mx[h] = fmaxf(mx[h], __shfl_xor_sync(0xFFFFFFFFu, mx[h], off));
        // pass 2: exp-sum
        float sm[8] = {0.f, 0.f, 0.f, 0.f, 0.f, 0.f, 0.f, 0.f};
        for (int j = lane; j < deg; j += 32) {
            int s = g_csrc[rs + j];
#pragma unroll
            for (int h = 0; h < 8; h++) {
                float sc = g_s1s[s * 8 + h] + sd[h];
                sc = sc > 0.f ? sc : 0.2f * sc;
                sm[h] += expf(sc - mx[h]);
            }
        }
#pragma unroll
        for (int h = 0; h < 8; h++)
#pragma unroll
            for (int off = 16; off; off >>= 1)
                sm[h] += __shfl_xor_sync(0xFFFFFFFFu, sm[h], off);
        float inv[8];
#pragma unroll
        for (int h = 0; h < 8; h++) inv[h] = 1.f / (sm[h] + 1e-16f);
        // per-lane (head = lane&7) params, selected without dynamic reg indexing
        int lh = lane & 7;
        float mxl = mx[0], invl = inv[0], sdl = sd[0];
#pragma unroll
        for (int h = 1; h < 8; h++)
            if (lh == h) { mxl = mx[h]; invl = inv[h]; sdl = sd[h]; }
        // pass 3: weighted accumulate
        for (int j = 0; j < deg; j++) {
            int s = g_csrc[rs + j];
            float sc = g_s1s[s * 8 + lh] + sdl;
            sc = sc > 0.f ? sc : 0.2f * sc;
            float al = expf(sc - mxl) * invl;
            const float* hp = g_h1 + s * HF;
#pragma unroll
            for (int k = 0; k < 8; k++) {
                float a = __shfl_sync(0xFFFFFFFFu, al, k);
                acc[k] += a * hp[k * 32 + lane];
            }
        }
    }
    // bias + ELU, store layer-2 input
#pragma unroll
    for (int k = 0; k < 8; k++) {
        float o = acc[k] + b1[k * 32 + lane];
        o = o > 0.f ? o : expm1f(o);
        g_out1[w * HF + k * 32 + lane] = o;
    }
}

// ---------------- GEMM2 + layer-2 attention dots: warp per node ----------------
__global__ void k_gemm2(const float* __restrict__ W2, const float* __restrict__ as2,
                        const float* __restrict__ ad2) {
    __shared__ float W2t[16][256];  // transposed: [c][k]
    int t = threadIdx.x;
    for (int i = t; i < 4096; i += blockDim.x) {
        int k = i >> 4, c = i & 15;
        W2t[c][k] = W2[i];
    }
    __syncthreads();
    int lane = t & 31, wid = t >> 5;
    for (int n = blockIdx.x * 8 + wid; n < NN; n += gridDim.x * 8) {
        const float* xp = g_out1 + n * HF;
        float v[8];
#pragma unroll
        for (int k = 0; k < 8; k++) v[k] = xp[k * 32 + lane];
        float acc[16];
#pragma unroll
        for (int c = 0; c < 16; c++) acc[c] = 0.f;
#pragma unroll
        for (int k = 0; k < 8; k++)
#pragma unroll
            for (int c = 0; c < 16; c++) acc[c] += v[k] * W2t[c][k * 32 + lane];
#pragma unroll
        for (int c = 0; c < 16; c++)
#pragma unroll
            for (int off = 16; off; off >>= 1)
                acc[c] += __shfl_xor_sync(0xFFFFFFFFu, acc[c], off);
        float h2v = acc[0];
#pragma unroll
        for (int c = 1; c < 16; c++)
            if ((lane & 15) == c) h2v = acc[c];
        if (lane < 16) g_h2[n * CC + lane] = h2v;
        float ps = (lane < 16) ? h2v * as2[lane] : 0.f;
        float pd = (lane < 16) ? h2v * ad2[lane] : 0.f;
#pragma unroll
        for (int off = 16; off; off >>= 1) {
            ps += __shfl_xor_sync(0xFFFFFFFFu, ps, off);
            pd += __shfl_xor_sync(0xFFFFFFFFu, pd, off);
        }
        if (lane == 0) { g_s2s[n] = ps; g_s2d[n] = pd; }
    }
}

// ---------------- layer-2 aggregation: warp per destination node ----------------
__global__ void k_agg2(const float* __restrict__ b2, float* __restrict__ out) {
    int gt = blockIdx.x * blockDim.x + threadIdx.x;
    int w = gt >> 5;
    int lane = threadIdx.x & 31;
    if (w >= NN) return;
    int rs = g_rs[w], re = g_rs[w + 1];
    int deg = re - rs;
    float acc = 0.f;
    if (deg > 0) {
        float sd = g_s2d[w];
        float mx = -1e30f;
        for (int j = lane; j < deg; j += 32) {
            int s = g_csrc[rs + j];
            float sc = g_s2s[s] + sd;
            sc = sc > 0.f ? sc : 0.2f * sc;
            mx = fmaxf(mx, sc);
        }
#pragma unroll
        for (int off = 16; off; off >>= 1)
            mx = fmaxf(mx, __shfl_xor_sync(0xFFFFFFFFu, mx, off));
        float sm = 0.f;
        for (int j = lane; j < deg; j += 32) {
            int s = g_csrc[rs + j];
            float sc = g_s2s[s] + sd;
            sc = sc > 0.f ? sc : 0.2f * sc;
            sm += expf(sc - mx);
        }
#pragma unroll
        for (int off = 16; off; off >>= 1)
            sm += __shfl_xor_sync(0xFFFFFFFFu, sm, off);
        float inv = 1.f / (sm + 1e-16f);
        for (int j = 0; j < deg; j++) {
            int s = g_csrc[rs + j];
            float sc = g_s2s[s] + sd;
            sc = sc > 0.f ? sc : 0.2f * sc;
            float al = expf(sc - mx) * inv;
            acc += al * g_h2[s * CC + (lane & 15)];
        }
    }
    if (lane < 16) out[w * CC + lane] = acc + b2[lane];
}

// ---------------- launch ----------------
extern "C" void kernel_launch(void* const* d_in, const int* in_sizes, int n_in,
                              void* d_out, int out_size) {
    const float* x = (const float*)d_in[0];
    const int* ei = (const int*)d_in[1];   // JAX x64 disabled -> int32 edge_index
    const float* W1 = (const float*)d_in[2];
    const float* as1 = (const float*)d_in[3];
    const float* ad1 = (const float*)d_in[4];
    const float* b1 = (const float*)d_in[5];
    const float* W2 = (const float*)d_in[6];
    const float* as2 = (const float*)d_in[7];
    const float* ad2 = (const float*)d_in[8];
    const float* b2 = (const float*)d_in[9];
    float* out = (float*)d_out;

    // CSR build
    k_zero<<<(NN + 255) / 256, 256>>>();
    k_hist<<<(NE + 255) / 256, 256>>>(ei);
    k_scanA<<<NB_SCAN, 1024>>>();
    k_scanB<<<1, 128>>>();
    k_scanC<<<(NN + 255) / 256, 256>>>();
    k_scatter<<<(NE + 255) / 256, 256>>>(ei);

    // layer 1
    k_gemm1<<<dim3((NN + 63) / 64, HF / 64), 256>>>(x, W1);
    k_sdot1<<<(NN * 32 + 255) / 256, 256>>>(as1, ad1);
    k_agg1<<<(NN * 32 + 255) / 256, 256>>>(b1);

    // layer 2
    k_gemm2<<<1024, 256>>>(W2, as2, ad2);
    k_agg2<<<(NN * 32 + 255) / 256, 256>>>(b2, out);
}

// round 4
// speedup vs baseline: 1.1281x; 1.1281x over previous
#include <cuda_runtime.h>
#include <cuda_fp16.h>

#define NN 100000
#define NE 1000000
#define FIN 128
#define HH 8
#define HF 256
#define CC 16
#define NB_SCAN ((NN + 1023) / 1024)
#define FULL 0xFFFFFFFFu

// ---------------- scratch (static device globals; no allocation) ----------------
__device__ __align__(16) float g_h1[NN * HF];     // fp32 features (for scores)
__device__ __align__(16) __half g_h1h[NN * HF];   // fp16 features (for message gather)
__device__ __align__(16) float g_out1[NN * HF];   // elu(layer-1 output)
__device__ __align__(16) float g_s1s[NN * HH];
__device__ __align__(16) float g_s1d[NN * HH];
__device__ __align__(16) float g_h2[NN * CC];
__device__ float g_s2s[NN];
__device__ float g_s2d[NN];
__device__ __align__(16) float g_w1[NE * HH];     // layer-1 edge weights (CSR order)
__device__ float g_w2[NE];                        // layer-2 edge weights (CSR order)
__device__ int g_deg[NN];
__device__ int g_cur[NN];
__device__ int g_rs[NN + 1];
__device__ int g_csrc[NE];
__device__ int g_pos[NE];                         // edge e -> CSR slot
__device__ int g_bsum[128];

// ---------------- CSR construction ----------------
__global__ void k_zero() {
    int i = blockIdx.x * blockDim.x + threadIdx.x;
    if (i < NN) { g_deg[i] = 0; g_cur[i] = 0; }
}

__global__ void k_hist(const int* __restrict__ ei) {
    int e = blockIdx.x * blockDim.x + threadIdx.x;
    if (e < NE) atomicAdd(&g_deg[ei[NE + e]], 1);
}

__global__ void k_scanA() {
    __shared__ int s[1024];
    int t = threadIdx.x;
    int i = blockIdx.x * 1024 + t;
    int v = (i < NN) ? g_deg[i] : 0;
    s[t] = v;
    __syncthreads();
    for (int off = 1; off < 1024; off <<= 1) {
        int u = (t >= off) ? s[t - off] : 0;
        __syncthreads();
        s[t] += u;
        __syncthreads();
    }
    if (i < NN) g_rs[i] = s[t] - v;
    if (t == 1023) g_bsum[blockIdx.x] = s[1023];
}

__global__ void k_scanB() {
    __shared__ int s[128];
    int t = threadIdx.x;
    int v = (t < NB_SCAN) ? g_bsum[t] : 0;
    s[t] = v;
    __syncthreads();
    for (int off = 1; off < 128; off <<= 1) {
        int u = (t >= off) ? s[t - off] : 0;
        __syncthreads();
        s[t] += u;
        __syncthreads();
    }
    if (t < NB_SCAN) g_bsum[t] = s[t] - v;
}

__global__ void k_scanC() {
    int i = blockIdx.x * blockDim.x + threadIdx.x;
    if (i < NN) g_rs[i] += g_bsum[i >> 10];
    if (i == 0) g_rs[NN] = NE;
}

__global__ void k_scatter(const int* __restrict__ ei) {
    int e = blockIdx.x * blockDim.x + threadIdx.x;
    if (e < NE) {
        int d = ei[NE + e];
        int p = atomicAdd(&g_cur[d], 1);
        int pos = g_rs[d] + p;
        g_csrc[pos] = ei[e];
        g_pos[e] = pos;
    }
}

// ---------------- GEMM1: h1 = x @ W1  (100000x128 @ 128x256) ----------------
__global__ void __launch_bounds__(256) k_gemm1(const float* __restrict__ x,
                                               const float* __restrict__ W1) {
    __shared__ __align__(16) float Xs[64][64];  // [k][m]
    __shared__ __align__(16) float Ws[64][64];  // [k][n]
    int bm = blockIdx.x * 64;
    int bn = blockIdx.y * 64;
    int t = threadIdx.x;
    int tx = t & 15, ty = t >> 4;
    float acc[4][4] = {};

#pragma unroll
    for (int kt = 0; kt < 2; kt++) {
#pragma unroll
        for (int it = 0; it < 4; it++) {
            int i = t + 256 * it;
            int r = i >> 4, k4 = i & 15;
            int row = bm + r;
            float4 v = (row < NN)
                ? *(const float4*)(x + row * FIN + kt * 64 + k4 * 4)
                : make_float4(0.f, 0.f, 0.f, 0.f);
            Xs[k4 * 4 + 0][r] = v.x;
            Xs[k4 * 4 + 1][r] = v.y;
            Xs[k4 * 4 + 2][r] = v.z;
            Xs[k4 * 4 + 3][r] = v.w;
        }
#pragma unroll
        for (int it = 0; it < 4; it++) {
            int i = t + 256 * it;
            int k = i >> 4, c4 = i & 15;
            *(float4*)&Ws[k][c4 * 4] =
                *(const float4*)(W1 + (kt * 64 + k) * HF + bn + c4 * 4);
        }
        __syncthreads();

#pragma unroll 16
        for (int k = 0; k < 64; k++) {
            float4 a = *(const float4*)&Xs[k][ty * 4];
            float4 b = *(const float4*)&Ws[k][tx * 4];
            acc[0][0] += a.x * b.x; acc[0][1] += a.x * b.y; acc[0][2] += a.x * b.z; acc[0][3] += a.x * b.w;
            acc[1][0] += a.y * b.x; acc[1][1] += a.y * b.y; acc[1][2] += a.y * b.z; acc[1][3] += a.y * b.w;
            acc[2][0] += a.z * b.x; acc[2][1] += a.z * b.y; acc[2][2] += a.z * b.z; acc[2][3] += a.z * b.w;
            acc[3][0] += a.w * b.x; acc[3][1] += a.w * b.y; acc[3][2] += a.w * b.z; acc[3][3] += a.w * b.w;
        }
        __syncthreads();
    }
#pragma unroll
    for (int i = 0; i < 4; i++) {
        int row = bm + ty * 4 + i;
        if (row < NN) {
            float4 v = make_float4(acc[i][0], acc[i][1], acc[i][2], acc[i][3]);
            *(float4*)&g_h1[row * HF + bn + tx * 4] = v;
            __half2 p0 = __floats2half2_rn(v.x, v.y);
            __half2 p1 = __floats2half2_rn(v.z, v.w);
            *(__half2*)(g_h1h + row * HF + bn + tx * 4) = p0;
            *(__half2*)(g_h1h + row * HF + bn + tx * 4 + 2) = p1;
        }
    }
}

// ---------------- per-node attention dot products, layer 1 ----------------
__global__ void k_sdot1(const float* __restrict__ as, const float* __restrict__ ad) {
    int gt = blockIdx.x * blockDim.x + threadIdx.x;
    int w = gt >> 5;
    int lane = threadIdx.x & 31;
    if (w >= NN) return;
    const float* hp = g_h1 + w * HF;
    float hv[8];
#pragma unroll
    for (int k = 0; k < 8; k++) hv[k] = hp[k * 32 + lane];
#pragma unroll
    for (int h = 0; h < 8; h++) {
        float ps = hv[h] * as[h * 32 + lane];
        float pd = hv[h] * ad[h * 32 + lane];
#pragma unroll
        for (int off = 16; off; off >>= 1) {
            ps += __shfl_xor_sync(FULL, ps, off);
            pd += __shfl_xor_sync(FULL, pd, off);
        }
        if (lane == 0) { g_s1s[w * 8 + h] = ps; g_s1d[w * 8 + h] = pd; }
    }
}

// ---------------- edge weights, layer 1 (no-max softmax numerator) ----------------
__global__ void k_w1(const int* __restrict__ ei) {
    int e = blockIdx.x * blockDim.x + threadIdx.x;
    if (e >= NE) return;
    int s = ei[e], d = ei[NE + e];
    int pos = g_pos[e];
    float4 ss0 = *(const float4*)&g_s1s[s * 8];
    float4 ss1 = *(const float4*)&g_s1s[s * 8 + 4];
    float4 sd0 = *(const float4*)&g_s1d[d * 8];
    float4 sd1 = *(const float4*)&g_s1d[d * 8 + 4];
    float sc[8] = {ss0.x + sd0.x, ss0.y + sd0.y, ss0.z + sd0.z, ss0.w + sd0.w,
                   ss1.x + sd1.x, ss1.y + sd1.y, ss1.z + sd1.z, ss1.w + sd1.w};
    float wv[8];
#pragma unroll
    for (int h = 0; h < 8; h++) {
        float v = sc[h] > 0.f ? sc[h] : 0.2f * sc[h];
        wv[h] = __expf(v);
    }
    *(float4*)&g_w1[pos * 8] = make_float4(wv[0], wv[1], wv[2], wv[3]);
    *(float4*)&g_w1[pos * 8 + 4] = make_float4(wv[4], wv[5], wv[6], wv[7]);
}

// ---------------- layer-1 aggregation: warp per destination node, single pass ----------------
__global__ void __launch_bounds__(256) k_agg1(const float* __restrict__ b1) {
    int gt = blockIdx.x * blockDim.x + threadIdx.x;
    int w = gt >> 5;
    int lane = threadIdx.x & 31;
    if (w >= NN) return;
    int rs = g_rs[w];
    int deg = g_rs[w + 1] - rs;
    int lh = lane & 7;
    int hsub = lane >> 4;  // which half of the 64-feature group (head parity)

    // sum of weights per head (lane l accumulates head l&7, edges strided by 4)
    float sm = 0.f;
    for (int j = (lane >> 3); j < deg; j += 4)
        sm += g_w1[(rs + j) * 8 + lh];
    sm += __shfl_xor_sync(FULL, sm, 8);
    sm += __shfl_xor_sync(FULL, sm, 16);
    float inv = 1.f / (sm + 1e-16f);

    // unnormalized weighted accumulate; lane owns features k*64 + lane*2 + {0,1}
    float acc[8] = {0.f, 0.f, 0.f, 0.f, 0.f, 0.f, 0.f, 0.f};
    int j = 0;
    for (; j + 2 <= deg; j += 2) {
        int p0 = rs + j, p1 = rs + j + 1;
        int s0 = g_csrc[p0], s1 = g_csrc[p1];
        float w0 = g_w1[p0 * 8 + lh];
        float w1 = g_w1[p1 * 8 + lh];
        const __half2* hp0 = (const __half2*)(g_h1h + s0 * HF);
        const __half2* hp1 = (const __half2*)(g_h1h + s1 * HF);
#pragma unroll
        for (int k = 0; k < 4; k++) {
            float2 f0 = __half22float2(hp0[k * 32 + lane]);
            float2 f1 = __half22float2(hp1[k * 32 + lane]);
            float wk0 = __shfl_sync(FULL, w0, k * 2 + hsub);
            float wk1 = __shfl_sync(FULL, w1, k * 2 + hsub);
            acc[2 * k]     += wk0 * f0.x + wk1 * f1.x;
            acc[2 * k + 1] += wk0 * f0.y + wk1 * f1.y;
        }
    }
    if (j < deg) {
        int p0 = rs + j;
        int s0 = g_csrc[p0];
        float w0 = g_w1[p0 * 8 + lh];
        const __half2* hp0 = (const __half2*)(g_h1h + s0 * HF);
#pragma unroll
        for (int k = 0; k < 4; k++) {
            float2 f0 = __half22float2(hp0[k * 32 + lane]);
            float wk0 = __shfl_sync(FULL, w0, k * 2 + hsub);
            acc[2 * k]     += wk0 * f0.x;
            acc[2 * k + 1] += wk0 * f0.y;
        }
    }

    // normalize + bias + ELU, store layer-2 input
#pragma unroll
    for (int k = 0; k < 4; k++) {
        float invk = __shfl_sync(FULL, inv, k * 2 + hsub);
        int f = k * 64 + lane * 2;
        float2 bv = *(const float2*)&b1[f];
        float o0 = acc[2 * k] * invk + bv.x;
        float o1 = acc[2 * k + 1] * invk + bv.y;
        o0 = o0 > 0.f ? o0 : expm1f(o0);
        o1 = o1 > 0.f ? o1 : expm1f(o1);
        *(float2*)&g_out1[w * HF + f] = make_float2(o0, o1);
    }
}

// ---------------- GEMM2 + layer-2 attention dots: warp per node ----------------
__global__ void k_gemm2(const float* __restrict__ W2, const float* __restrict__ as2,
                        const float* __restrict__ ad2) {
    __shared__ float W2t[16][256];  // transposed: [c][k]
    int t = threadIdx.x;
    for (int i = t; i < 4096; i += blockDim.x) {
        int k = i >> 4, c = i & 15;
        W2t[c][k] = W2[i];
    }
    __syncthreads();
    int lane = t & 31, wid = t >> 5;
    for (int n = blockIdx.x * 8 + wid; n < NN; n += gridDim.x * 8) {
        const float* xp = g_out1 + n * HF;
        float v[8];
#pragma unroll
        for (int k = 0; k < 8; k++) v[k] = xp[k * 32 + lane];
        float acc[16];
#pragma unroll
        for (int c = 0; c < 16; c++) acc[c] = 0.f;
#pragma unroll
        for (int k = 0; k < 8; k++)
#pragma unroll
            for (int c = 0; c < 16; c++) acc[c] += v[k] * W2t[c][k * 32 + lane];
#pragma unroll
        for (int c = 0; c < 16; c++)
#pragma unroll
            for (int off = 16; off; off >>= 1)
                acc[c] += __shfl_xor_sync(FULL, acc[c], off);
        float h2v = acc[0];
#pragma unroll
        for (int c = 1; c < 16; c++)
            if ((lane & 15) == c) h2v = acc[c];
        if (lane < 16) g_h2[n * CC + lane] = h2v;
        float ps = (lane < 16) ? h2v * as2[lane] : 0.f;
        float pd = (lane < 16) ? h2v * ad2[lane] : 0.f;
#pragma unroll
        for (int off = 16; off; off >>= 1) {
            ps += __shfl_xor_sync(FULL, ps, off);
            pd += __shfl_xor_sync(FULL, pd, off);
        }
        if (lane == 0) { g_s2s[n] = ps; g_s2d[n] = pd; }
    }
}

// ---------------- edge weights, layer 2 ----------------
__global__ void k_w2(const int* __restrict__ ei) {
    int e = blockIdx.x * blockDim.x + threadIdx.x;
    if (e >= NE) return;
    int s = ei[e], d = ei[NE + e];
    float sc = g_s2s[s] + g_s2d[d];
    sc = sc > 0.f ? sc : 0.2f * sc;
    g_w2[g_pos[e]] = __expf(sc);
}

// ---------------- layer-2 aggregation: warp per dst node, half-warps split edges ----------------
__global__ void __launch_bounds__(256) k_agg2(const float* __restrict__ b2,
                                              float* __restrict__ out) {
    int gt = blockIdx.x * blockDim.x + threadIdx.x;
    int w = gt >> 5;
    int lane = threadIdx.x & 31;
    if (w >= NN) return;
    int rs = g_rs[w];
    int deg = g_rs[w + 1] - rs;
    int half = lane >> 4, l15 = lane & 15;

    // weight sum (lane-parallel)
    float sm = 0.f;
    for (int j = lane; j < deg; j += 32) sm += g_w2[rs + j];
#pragma unroll
    for (int off = 16; off; off >>= 1) sm += __shfl_xor_sync(FULL, sm, off);
    float inv = 1.f / (sm + 1e-16f);

    // accumulate: half-warp 0 takes even edges, half-warp 1 odd edges
    float acc = 0.f;
    for (int j = half; j < deg; j += 2) {
        int p = rs + j;
        int s = g_csrc[p];
        float wv = g_w2[p];
        acc += wv * g_h2[s * CC + l15];
    }
    acc += __shfl_xor_sync(FULL, acc, 16);
    if (lane < 16) out[w * CC + l15] = acc * inv + b2[l15];
}

// ---------------- launch ----------------
extern "C" void kernel_launch(void* const* d_in, const int* in_sizes, int n_in,
                              void* d_out, int out_size) {
    const float* x = (const float*)d_in[0];
    const int* ei = (const int*)d_in[1];   // JAX x64 disabled -> int32 edge_index
    const float* W1 = (const float*)d_in[2];
    const float* as1 = (const float*)d_in[3];
    const float* ad1 = (const float*)d_in[4];
    const float* b1 = (const float*)d_in[5];
    const float* W2 = (const float*)d_in[6];
    const float* as2 = (const float*)d_in[7];
    const float* ad2 = (const float*)d_in[8];
    const float* b2 = (const float*)d_in[9];
    float* out = (float*)d_out;

    // CSR build
    k_zero<<<(NN + 255) / 256, 256>>>();
    k_hist<<<(NE + 255) / 256, 256>>>(ei);
    k_scanA<<<NB_SCAN, 1024>>>();
    k_scanB<<<1, 128>>>();
    k_scanC<<<(NN + 255) / 256, 256>>>();
    k_scatter<<<(NE + 255) / 256, 256>>>(ei);

    // layer 1
    k_gemm1<<<dim3((NN + 63) / 64, HF / 64), 256>>>(x, W1);
    k_sdot1<<<(NN * 32 + 255) / 256, 256>>>(as1, ad1);
    k_w1<<<(NE + 255) / 256, 256>>>(ei);
    k_agg1<<<(NN * 32 + 255) / 256, 256>>>(b1);

    // layer 2
    k_gemm2<<<1024, 256>>>(W2, as2, ad2);
    k_w2<<<(NE + 255) / 256, 256>>>(ei);
    k_agg2<<<(NN * 32 + 255) / 256, 256>>>(b2, out);
}

// round 6
// speedup vs baseline: 1.4060x; 1.2463x over previous
#include <cuda_runtime.h>
#include <cuda_fp16.h>

#define NN 100000
#define NE 1000000
#define FIN 128
#define HH 8
#define HF 256
#define CC 16
#define NB_SCAN ((NN + 1023) / 1024)
#define FULL 0xFFFFFFFFu

// ---------------- scratch (static device globals; no allocation) ----------------
__device__ __align__(16) __half g_h1h[NN * HF];   // fp16 features (message gather)
__device__ __align__(16) float g_out1[NN * HF];   // elu(layer-1 output)
__device__ __align__(16) float g_s1s[NN * HH];
__device__ __align__(16) float g_s1d[NN * HH];
__device__ __align__(16) float g_h2[NN * CC];
__device__ float g_s2s[NN];
__device__ float g_s2d[NN];
__device__ __align__(16) float g_w1[NE * HH];     // layer-1 edge weights (CSR order)
__device__ float g_w2[NE];                        // layer-2 edge weights (CSR order)
__device__ int g_deg[NN];
__device__ int g_cur[NN];
__device__ int g_rs[NN + 1];
__device__ int g_csrc[NE];
__device__ int g_pos[NE];                         // edge e -> CSR slot
__device__ int g_bsum[128];

// ---------------- CSR construction ----------------
__global__ void k_zero() {
    int i = blockIdx.x * blockDim.x + threadIdx.x;
    if (i < NN) { g_deg[i] = 0; g_cur[i] = 0; }
}

__global__ void k_hist(const int* __restrict__ ei) {
    int e = blockIdx.x * blockDim.x + threadIdx.x;
    if (e < NE) atomicAdd(&g_deg[ei[NE + e]], 1);
}

__global__ void k_scanA() {
    __shared__ int s[1024];
    int t = threadIdx.x;
    int i = blockIdx.x * 1024 + t;
    int v = (i < NN) ? g_deg[i] : 0;
    s[t] = v;
    __syncthreads();
    for (int off = 1; off < 1024; off <<= 1) {
        int u = (t >= off) ? s[t - off] : 0;
        __syncthreads();
        s[t] += u;
        __syncthreads();
    }
    if (i < NN) g_rs[i] = s[t] - v;
    if (t == 1023) g_bsum[blockIdx.x] = s[1023];
}

__global__ void k_scanB() {
    __shared__ int s[128];
    int t = threadIdx.x;
    int v = (t < NB_SCAN) ? g_bsum[t] : 0;
    s[t] = v;
    __syncthreads();
    for (int off = 1; off < 128; off <<= 1) {
        int u = (t >= off) ? s[t - off] : 0;
        __syncthreads();
        s[t] += u;
        __syncthreads();
    }
    if (t < NB_SCAN) g_bsum[t] = s[t] - v;
}

__global__ void k_scanC() {
    int i = blockIdx.x * blockDim.x + threadIdx.x;
    if (i < NN) g_rs[i] += g_bsum[i >> 10];
    if (i == 0) g_rs[NN] = NE;
}

__global__ void k_scatter(const int* __restrict__ ei) {
    int e = blockIdx.x * blockDim.x + threadIdx.x;
    if (e < NE) {
        int d = ei[NE + e];
        int p = atomicAdd(&g_cur[d], 1);
        int pos = g_rs[d] + p;
        g_csrc[pos] = ei[e];
        g_pos[e] = pos;
    }
}

// ---------------- GEMM1 + score epilogue ----------------
// 128x128 tile, 256 threads, 8x8 micro-kernel, K-tile 32.
// Epilogue: fp16 feature store + per-head attention dots (s1s/s1d) via quad shuffle.
__global__ void __launch_bounds__(256) k_gemm1(const float* __restrict__ x,
                                               const float* __restrict__ W1,
                                               const float* __restrict__ as1,
                                               const float* __restrict__ ad1) {
    __shared__ float Xs[128][33];   // [m][k], padded
    __shared__ __align__(16) float Ws[32][128];  // [k][n]
    int bm = blockIdx.x * 128;
    int bn = blockIdx.y * 128;
    int t = threadIdx.x;
    int tx = t & 15, ty = t >> 4;
    float acc[8][8];
#pragma unroll
    for (int i = 0; i < 8; i++)
#pragma unroll
        for (int j = 0; j < 8; j++) acc[i][j] = 0.f;

#pragma unroll
    for (int kt = 0; kt < 4; kt++) {
        // Xs: 128 rows x 32 k (1024 float4 / 256 threads = 4 each)
#pragma unroll
        for (int it = 0; it < 4; it++) {
            int idx = t + 256 * it;
            int r = idx >> 3, kc = idx & 7;
            int row = bm + r;
            float4 v = (row < NN)
                ? *(const float4*)(x + row * FIN + kt * 32 + kc * 4)
                : make_float4(0.f, 0.f, 0.f, 0.f);
            Xs[r][kc * 4 + 0] = v.x;
            Xs[r][kc * 4 + 1] = v.y;
            Xs[r][kc * 4 + 2] = v.z;
            Xs[r][kc * 4 + 3] = v.w;
        }
        // Ws: 32 k x 128 n (1024 float4 / 256 = 4 each)
#pragma unroll
        for (int it = 0; it < 4; it++) {
            int idx = t + 256 * it;
            int k = idx >> 5, nc = idx & 31;
            *(float4*)&Ws[k][nc * 4] =
                *(const float4*)(W1 + (kt * 32 + k) * HF + bn + nc * 4);
        }
        __syncthreads();

#pragma unroll 8
        for (int k = 0; k < 32; k++) {
            float a[8];
#pragma unroll
            for (int i = 0; i < 8; i++) a[i] = Xs[ty * 8 + i][k];
            float4 b0 = *(const float4*)&Ws[k][tx * 8];
            float4 b1 = *(const float4*)&Ws[k][tx * 8 + 4];
#pragma unroll
            for (int i = 0; i < 8; i++) {
                acc[i][0] += a[i] * b0.x; acc[i][1] += a[i] * b0.y;
                acc[i][2] += a[i] * b0.z; acc[i][3] += a[i] * b0.w;
                acc[i][4] += a[i] * b1.x; acc[i][5] += a[i] * b1.y;
                acc[i][6] += a[i] * b1.z; acc[i][7] += a[i] * b1.w;
            }
        }
        __syncthreads();
    }

    // attention-vector slice for this thread's 8 columns (one head per tx-quad)
    int head = (bn >> 5) + (tx >> 2);          // bn/32 + tx/4
    int fbase = (tx & 3) * 8;                  // feature offset within head
    float av[8], dv[8];
#pragma unroll
    for (int j = 0; j < 8; j++) {
        av[j] = as1[head * 32 + fbase + j];
        dv[j] = ad1[head * 32 + fbase + j];
    }

#pragma unroll
    for (int i = 0; i < 8; i++) {
        int row = bm + ty * 8 + i;
        bool ok = row < NN;
        // fp16 feature store (8 halves = 16B)
        if (ok) {
            __half2 p[4];
#pragma unroll
            for (int q = 0; q < 4; q++)
                p[q] = __floats2half2_rn(acc[i][2 * q], acc[i][2 * q + 1]);
            *(uint4*)(g_h1h + row * HF + bn + tx * 8) = *(uint4*)p;
        }
        // per-head dot products, reduced over the tx-quad (lane bits 0,1)
        float ss = 0.f, sd = 0.f;
#pragma unroll
        for (int j = 0; j < 8; j++) { ss += acc[i][j] * av[j]; sd += acc[i][j] * dv[j]; }
        ss += __shfl_xor_sync(FULL, ss, 1); sd += __shfl_xor_sync(FULL, sd, 1);
        ss += __shfl_xor_sync(FULL, ss, 2); sd += __shfl_xor_sync(FULL, sd, 2);
        if (ok && (tx & 3) == 0) {
            g_s1s[row * 8 + head] = ss;
            g_s1d[row * 8 + head] = sd;
        }
    }
}

// ---------------- edge weights, layer 1 (no-max softmax numerator) ----------------
__global__ void k_w1(const int* __restrict__ ei) {
    int e = blockIdx.x * blockDim.x + threadIdx.x;
    if (e >= NE) return;
    int s = ei[e], d = ei[NE + e];
    int pos = g_pos[e];
    float4 ss0 = *(const float4*)&g_s1s[s * 8];
    float4 ss1 = *(const float4*)&g_s1s[s * 8 + 4];
    float4 sd0 = *(const float4*)&g_s1d[d * 8];
    float4 sd1 = *(const float4*)&g_s1d[d * 8 + 4];
    float sc[8] = {ss0.x + sd0.x, ss0.y + sd0.y, ss0.z + sd0.z, ss0.w + sd0.w,
                   ss1.x + sd1.x, ss1.y + sd1.y, ss1.z + sd1.z, ss1.w + sd1.w};
    float wv[8];
#pragma unroll
    for (int h = 0; h < 8; h++) {
        float v = sc[h] > 0.f ? sc[h] : 0.2f * sc[h];
        wv[h] = __expf(v);
    }
    *(float4*)&g_w1[pos * 8] = make_float4(wv[0], wv[1], wv[2], wv[3]);
    *(float4*)&g_w1[pos * 8 + 4] = make_float4(wv[4], wv[5], wv[6], wv[7]);
}

// ---------------- layer-1 aggregation: warp per dst node, single pass, fused sum ----------------
__global__ void __launch_bounds__(256) k_agg1(const float* __restrict__ b1) {
    int gt = blockIdx.x * blockDim.x + threadIdx.x;
    int w = gt >> 5;
    int lane = threadIdx.x & 31;
    if (w >= NN) return;
    int rs = g_rs[w];
    int deg = g_rs[w + 1] - rs;
    int lh = lane & 7;
    int hsub = lane >> 4;

    float sm = 0.f;
    float acc[8] = {0.f, 0.f, 0.f, 0.f, 0.f, 0.f, 0.f, 0.f};
    int j = 0;
    for (; j + 2 <= deg; j += 2) {
        int p0 = rs + j, p1 = rs + j + 1;
        int s0 = g_csrc[p0], s1 = g_csrc[p1];
        float w0 = g_w1[p0 * 8 + lh];
        float w1 = g_w1[p1 * 8 + lh];
        sm += w0 + w1;
        const __half2* hp0 = (const __half2*)(g_h1h + s0 * HF);
        const __half2* hp1 = (const __half2*)(g_h1h + s1 * HF);
#pragma unroll
        for (int k = 0; k < 4; k++) {
            float2 f0 = __half22float2(hp0[k * 32 + lane]);
            float2 f1 = __half22float2(hp1[k * 32 + lane]);
            float wk0 = __shfl_sync(FULL, w0, k * 2 + hsub);
            float wk1 = __shfl_sync(FULL, w1, k * 2 + hsub);
            acc[2 * k]     += wk0 * f0.x + wk1 * f1.x;
            acc[2 * k + 1] += wk0 * f0.y + wk1 * f1.y;
        }
    }
    if (j < deg) {
        int p0 = rs + j;
        int s0 = g_csrc[p0];
        float w0 = g_w1[p0 * 8 + lh];
        sm += w0;
        const __half2* hp0 = (const __half2*)(g_h1h + s0 * HF);
#pragma unroll
        for (int k = 0; k < 4; k++) {
            float2 f0 = __half22float2(hp0[k * 32 + lane]);
            float wk0 = __shfl_sync(FULL, w0, k * 2 + hsub);
            acc[2 * k]     += wk0 * f0.x;
            acc[2 * k + 1] += wk0 * f0.y;
        }
    }
    float inv = 1.f / (sm + 1e-16f);

#pragma unroll
    for (int k = 0; k < 4; k++) {
        float invk = __shfl_sync(FULL, inv, k * 2 + hsub);
        int f = k * 64 + lane * 2;
        float2 bv = *(const float2*)&b1[f];
        float o0 = acc[2 * k] * invk + bv.x;
        float o1 = acc[2 * k + 1] * invk + bv.y;
        o0 = o0 > 0.f ? o0 : expm1f(o0);
        o1 = o1 > 0.f ? o1 : expm1f(o1);
        *(float2*)&g_out1[w * HF + f] = make_float2(o0, o1);
    }
}

// ---------------- GEMM2 + layer-2 attention dots: warp per node ----------------
__global__ void k_gemm2(const float* __restrict__ W2, const float* __restrict__ as2,
                        const float* __restrict__ ad2) {
    __shared__ float W2t[16][256];  // transposed: [c][k]
    int t = threadIdx.x;
    for (int i = t; i < 4096; i += blockDim.x) {
        int k = i >> 4, c = i & 15;
        W2t[c][k] = W2[i];
    }
    __syncthreads();
    int lane = t & 31, wid = t >> 5;
    for (int n = blockIdx.x * 8 + wid; n < NN; n += gridDim.x * 8) {
        const float* xp = g_out1 + n * HF;
        float v[8];
#pragma unroll
        for (int k = 0; k < 8; k++) v[k] = xp[k * 32 + lane];
        float acc[16];
#pragma unroll
        for (int c = 0; c < 16; c++) acc[c] = 0.f;
#pragma unroll
        for (int k = 0; k < 8; k++)
#pragma unroll
            for (int c = 0; c < 16; c++) acc[c] += v[k] * W2t[c][k * 32 + lane];
#pragma unroll
        for (int c = 0; c < 16; c++)
#pragma unroll
            for (int off = 16; off; off >>= 1)
                acc[c] += __shfl_xor_sync(FULL, acc[c], off);
        float h2v = acc[0];
#pragma unroll
        for (int c = 1; c < 16; c++)
            if ((lane & 15) == c) h2v = acc[c];
        if (lane < 16) g_h2[n * CC + lane] = h2v;
        float ps = (lane < 16) ? h2v * as2[lane] : 0.f;
        float pd = (lane < 16) ? h2v * ad2[lane] : 0.f;
#pragma unroll
        for (int off = 16; off; off >>= 1) {
            ps += __shfl_xor_sync(FULL, ps, off);
            pd += __shfl_xor_sync(FULL, pd, off);
        }
        if (lane == 0) { g_s2s[n] = ps; g_s2d[n] = pd; }
    }
}

// ---------------- edge weights, layer 2 ----------------
__global__ void k_w2(const int* __restrict__ ei) {
    int e = blockIdx.x * blockDim.x + threadIdx.x;
    if (e >= NE) return;
    int s = ei[e], d = ei[NE + e];
    float sc = g_s2s[s] + g_s2d[d];
    sc = sc > 0.f ? sc : 0.2f * sc;
    g_w2[g_pos[e]] = __expf(sc);
}

// ---------------- layer-2 aggregation ----------------
__global__ void __launch_bounds__(256) k_agg2(const float* __restrict__ b2,
                                              float* __restrict__ out) {
    int gt = blockIdx.x * blockDim.x + threadIdx.x;
    int w = gt >> 5;
    int lane = threadIdx.x & 31;
    if (w >= NN) return;
    int rs = g_rs[w];
    int deg = g_rs[w + 1] - rs;
    int half = lane >> 4, l15 = lane & 15;

    float sm = 0.f;
    float acc = 0.f;
    for (int j = half; j < deg; j += 2) {
        int p = rs + j;
        int s = g_csrc[p];
        float wv = g_w2[p];
        sm += wv;
        acc += wv * g_h2[s * CC + l15];
    }
    acc += __shfl_xor_sync(FULL, acc, 16);
    sm += __shfl_xor_sync(FULL, sm, 16);
    float inv = 1.f / (sm + 1e-16f);
    if (lane < 16) out[w * CC + l15] = acc * inv + b2[l15];
}

// ---------------- launch ----------------
extern "C" void kernel_launch(void* const* d_in, const int* in_sizes, int n_in,
                              void* d_out, int out_size) {
    const float* x = (const float*)d_in[0];
    const int* ei = (const int*)d_in[1];   // JAX x64 disabled -> int32 edge_index
    const float* W1 = (const float*)d_in[2];
    const float* as1 = (const float*)d_in[3];
    const float* ad1 = (const float*)d_in[4];
    const float* b1 = (const float*)d_in[5];
    const float* W2 = (const float*)d_in[6];
    const float* as2 = (const float*)d_in[7];
    const float* ad2 = (const float*)d_in[8];
    const float* b2 = (const float*)d_in[9];
    float* out = (float*)d_out;

    // CSR build
    k_zero<<<(NN + 255) / 256, 256>>>();
    k_hist<<<(NE + 255) / 256, 256>>>(ei);
    k_scanA<<<NB_SCAN, 1024>>>();
    k_scanB<<<1, 128>>>();
    k_scanC<<<(NN + 255) / 256, 256>>>();
    k_scatter<<<(NE + 255) / 256, 256>>>(ei);

    // layer 1
    k_gemm1<<<dim3((NN + 127) / 128, HF / 128), 256>>>(x, W1, as1, ad1);
    k_w1<<<(NE + 255) / 256, 256>>>(ei);
    k_agg1<<<(NN * 32 + 255) / 256, 256>>>(b1);

    // layer 2
    k_gemm2<<<1024, 256>>>(W2, as2, ad2);
    k_w2<<<(NE + 255) / 256, 256>>>(ei);
    k_agg2<<<(NN * 32 + 255) / 256, 256>>>(b2, out);
}